// round 11
// baseline (speedup 1.0000x reference)
#include <cuda_runtime.h>
#include <cuda_fp16.h>
#include <cstdint>
#include <cstddef>

#define NN 50000
#define NE 800000
#define DIN 128
#define DHID 512
#define DOUT 256

// ---------------------------------------------------------------------------
// Scratch (device globals — no runtime allocation)
// ---------------------------------------------------------------------------
__device__ __half g_xh[(size_t)NN * DIN];        // x in fp16 (gather source)
__device__ __half g_xhi[(size_t)NN * DIN];       // (x+agg) fp16
__device__ __half g_mhi[(size_t)NN * DHID];      // hmid fp16
__device__ float g_h2[(size_t)NN * DOUT];        // after layer2+act (fp32)
__device__ __half g_w1hi[(size_t)DHID * DIN];    // W1^T [N][K] fp16
__device__ __half g_w2hi[(size_t)DOUT * DHID];   // W2^T [N][K] fp16
__device__ float g_sum[DOUT];
__device__ float g_sumsq[DOUT];
// CSR build
__device__ int g_deg[NN];
__device__ int g_off[NN + 1];
__device__ int g_cur[NN];
__device__ int g_srcs[NE];

// ---------------------------------------------------------------------------
// PTX helpers
// ---------------------------------------------------------------------------
__device__ __forceinline__ uint32_t smem_u32(const void* p) {
    uint32_t a;
    asm("{ .reg .u64 t; cvta.to.shared.u64 t, %1; cvt.u32.u64 %0, t; }"
        : "=r"(a) : "l"(p));
    return a;
}
__device__ __forceinline__ void cp_async16(uint32_t dst, const void* src, bool pred) {
    int sz = pred ? 16 : 0;
    asm volatile("cp.async.cg.shared.global [%0], [%1], 16, %2;"
                 :: "r"(dst), "l"(src), "r"(sz));
}
__device__ __forceinline__ void cp_commit() {
    asm volatile("cp.async.commit_group;" ::: "memory");
}
__device__ __forceinline__ void cp_wait0() {
    asm volatile("cp.async.wait_group 0;" ::: "memory");
}
__device__ __forceinline__ void cp_wait1() {
    asm volatile("cp.async.wait_group 1;" ::: "memory");
}
__device__ __forceinline__ void cp_wait2() {
    asm volatile("cp.async.wait_group 2;" ::: "memory");
}
__device__ __forceinline__ void ldsm_x4(uint32_t* r, uint32_t addr) {
    asm volatile("ldmatrix.sync.aligned.m8n8.x4.shared.b16 {%0,%1,%2,%3}, [%4];"
                 : "=r"(r[0]), "=r"(r[1]), "=r"(r[2]), "=r"(r[3]) : "r"(addr));
}
__device__ __forceinline__ void hmma(float* c, const uint32_t* a, const uint32_t* b) {
    asm volatile(
        "mma.sync.aligned.m16n8k16.row.col.f32.f16.f16.f32 "
        "{%0,%1,%2,%3}, {%4,%5,%6,%7}, {%8,%9}, {%0,%1,%2,%3};"
        : "+f"(c[0]), "+f"(c[1]), "+f"(c[2]), "+f"(c[3])
        : "r"(a[0]), "r"(a[1]), "r"(a[2]), "r"(a[3]), "r"(b[0]), "r"(b[1]));
}

// ---------------------------------------------------------------------------
// 0) zero + convert x -> fp16
// ---------------------------------------------------------------------------
__global__ void k_zero() {
    int i = blockIdx.x * blockDim.x + threadIdx.x;
    if (i < NN) g_deg[i] = 0;
    if (i < DOUT) { g_sum[i] = 0.f; g_sumsq[i] = 0.f; }
}

__global__ void k_x2h(const float* __restrict__ x) {
    int i = blockIdx.x * blockDim.x + threadIdx.x;
    const int n4 = NN * DIN / 4;
    if (i >= n4) return;
    float4 v = reinterpret_cast<const float4*>(x)[i];
    __half2* o = reinterpret_cast<__half2*>(g_xh) + i * 2;
    o[0] = __halves2half2(__float2half_rn(v.x), __float2half_rn(v.y));
    o[1] = __halves2half2(__float2half_rn(v.z), __float2half_rn(v.w));
}

// ---------------------------------------------------------------------------
// 1) histogram of dst degrees
// ---------------------------------------------------------------------------
__global__ void k_hist(const int* __restrict__ ei) {
    int e = blockIdx.x * blockDim.x + threadIdx.x;
    if (e < NE) atomicAdd(&g_deg[ei[NE + e]], 1);
}

// ---------------------------------------------------------------------------
// 2) exclusive scan over degrees (single block)
// ---------------------------------------------------------------------------
__global__ void __launch_bounds__(1024) k_scan() {
    __shared__ int bs[1024];
    const int t = threadIdx.x;
    const int SEG = (NN + 1023) / 1024;
    int start = t * SEG;
    int stop = start + SEG < NN ? start + SEG : NN;
    int s = 0;
    for (int i = start; i < stop; i++) s += g_deg[i];
    bs[t] = s;
    __syncthreads();
    for (int d = 1; d < 1024; d <<= 1) {
        int u = (t >= d) ? bs[t - d] : 0;
        __syncthreads();
        if (t >= d) bs[t] += u;
        __syncthreads();
    }
    int run = bs[t] - s;
    for (int i = start; i < stop; i++) {
        g_off[i] = run;
        g_cur[i] = run;
        run += g_deg[i];
    }
    if (t == 1023) g_off[NN] = run;
}

// ---------------------------------------------------------------------------
// 3) bucket edges by dst
// ---------------------------------------------------------------------------
__global__ void k_bucket(const int* __restrict__ ei) {
    int e = blockIdx.x * blockDim.x + threadIdx.x;
    if (e >= NE) return;
    int dst = ei[NE + e];
    int pos = atomicAdd(&g_cur[dst], 1);
    g_srcs[pos] = ei[e];
}

// ---------------------------------------------------------------------------
// 4) aggregate: one warp per node; fp16 gather, fp32 accumulate, fp16 out
// ---------------------------------------------------------------------------
__global__ void __launch_bounds__(256) k_agg() {
    int w = (blockIdx.x * blockDim.x + threadIdx.x) >> 5;
    if (w >= NN) return;
    int lane = threadIdx.x & 31;

    // self row (fp16 source)
    float acc[4];
    {
        uint2 v = *reinterpret_cast<const uint2*>(g_xh + (size_t)w * DIN + lane * 4);
        __half2 h0 = *reinterpret_cast<__half2*>(&v.x);
        __half2 h1 = *reinterpret_cast<__half2*>(&v.y);
        float2 f0 = __half22float2(h0), f1 = __half22float2(h1);
        acc[0] = f0.x; acc[1] = f0.y; acc[2] = f1.x; acc[3] = f1.y;
    }
    int beg = g_off[w], end = g_off[w + 1];
    for (int base = beg; base < end; base += 32) {
        int n = end - base;
        if (n > 32) n = 32;
        int s = (lane < n) ? g_srcs[base + lane] : 0;
        #pragma unroll 4
        for (int j = 0; j < n; j++) {
            int src = __shfl_sync(0xffffffffu, s, j);
            uint2 v = *reinterpret_cast<const uint2*>(g_xh + (size_t)src * DIN + lane * 4);
            __half2 h0 = *reinterpret_cast<__half2*>(&v.x);
            __half2 h1 = *reinterpret_cast<__half2*>(&v.y);
            float2 f0 = __half22float2(h0), f1 = __half22float2(h1);
            acc[0] += f0.x; acc[1] += f0.y; acc[2] += f1.x; acc[3] += f1.y;
        }
    }
    __half2* o = reinterpret_cast<__half2*>(g_xhi + (size_t)w * DIN + lane * 4);
    o[0] = __halves2half2(__float2half_rn(acc[0]), __float2half_rn(acc[1]));
    o[1] = __halves2half2(__float2half_rn(acc[2]), __float2half_rn(acc[3]));
}

// ---------------------------------------------------------------------------
// 5) W [K,N] -> W^T [N,K] fp16
// ---------------------------------------------------------------------------
__global__ void k_prep_w(const float* __restrict__ W, __half* __restrict__ hi,
                         int K, int N) {
    int i = blockIdx.x * blockDim.x + threadIdx.x;
    if (i >= K * N) return;
    int n = i / K, k = i % K;
    hi[i] = __float2half_rn(W[(size_t)k * N + n]);
}

// ---------------------------------------------------------------------------
// 6) GEMM1 single-shot: hmid = lrelu(A @ W1^T + b1) -> fp16.
//    K=128 loaded in one cp.async wave. CTA 128x128, 8 warps (4m x 2n),
//    2 CTAs/SM. Row pad 256B->272B (68 words = 4 mod 32, conflict-free ldsm).
// ---------------------------------------------------------------------------
#define A1_ROWB 272
#define A1_SZ (128 * A1_ROWB)        // 34816
#define G1_A 0
#define G1_B A1_SZ
#define G1_SMEM (2 * A1_SZ)          // 69632 -> 2 CTAs/SM

__global__ void __launch_bounds__(256, 2)
k_gemm1(const __half* __restrict__ Ah, const __half* __restrict__ Bh,
        const float* __restrict__ bias, __half* __restrict__ Chi) {
    extern __shared__ char smem[];
    const uint32_t sb = smem_u32(smem);
    const int tid = threadIdx.x;
    const int wid = tid >> 5;
    const int lane = tid & 31;
    const int warp_m = wid & 3;
    const int warp_n = wid >> 2;
    const int m0 = blockIdx.y * 128;
    const int n0 = blockIdx.x * 128;
    const int M = NN, K = DIN, ldc = DHID;

    #pragma unroll
    for (int it = 0; it < 8; it++) {
        int idx = tid + it * 256;            // 0..2047
        int row = idx >> 4;                  // 0..127
        int c = idx & 15;                    // 16B chunk within 256B row
        uint32_t soff = (uint32_t)(row * A1_ROWB + c * 16);
        int gmr = m0 + row;
        cp_async16(sb + G1_A + soff, Ah + (size_t)gmr * K + c * 8, gmr < M);
        int gnr = n0 + row;
        cp_async16(sb + G1_B + soff, Bh + (size_t)gnr * K + c * 8, true);
    }
    cp_commit();
    cp_wait0();
    __syncthreads();

    float acc[2][8][4];
    #pragma unroll
    for (int a = 0; a < 2; a++)
        #pragma unroll
        for (int b = 0; b < 8; b++)
            #pragma unroll
            for (int c = 0; c < 4; c++) acc[a][b][c] = 0.f;

    const uint32_t lrow = (uint32_t)(lane & 15);
    const uint32_t lchk = (uint32_t)(lane >> 4);

    #pragma unroll
    for (int ks = 0; ks < 8; ks++) {
        uint32_t a_hi[2][4];
        #pragma unroll
        for (int mt = 0; mt < 2; mt++) {
            uint32_t r = (uint32_t)(warp_m * 32 + mt * 16) + lrow;
            ldsm_x4(a_hi[mt], sb + G1_A + r * A1_ROWB + lchk * 16 + ks * 32);
        }
        #pragma unroll
        for (int np = 0; np < 4; np++) {
            uint32_t bh[4];
            uint32_t r = (uint32_t)(warp_n * 64 + np * 16) + lrow;
            ldsm_x4(bh, sb + G1_B + r * A1_ROWB + lchk * 16 + ks * 32);
            uint32_t b0h[2] = {bh[0], bh[2]}, b1h[2] = {bh[1], bh[3]};
            #pragma unroll
            for (int mt = 0; mt < 2; mt++) {
                hmma(acc[mt][2 * np],     a_hi[mt], b0h);
                hmma(acc[mt][2 * np + 1], a_hi[mt], b1h);
            }
        }
    }

    #pragma unroll
    for (int mt = 0; mt < 2; mt++) {
        int row = m0 + warp_m * 32 + mt * 16 + (lane >> 2);
        #pragma unroll
        for (int nt = 0; nt < 8; nt++) {
            int col = n0 + warp_n * 64 + nt * 8 + 2 * (lane & 3);
            float bx = bias[col], by = bias[col + 1];
            #pragma unroll
            for (int h = 0; h < 2; h++) {
                int r = row + h * 8;
                if (r >= M) continue;
                float v0 = acc[mt][nt][2 * h + 0] + bx;
                float v1 = acc[mt][nt][2 * h + 1] + by;
                v0 = v0 > 0.f ? v0 : 0.01f * v0;
                v1 = v1 > 0.f ? v1 : 0.01f * v1;
                *reinterpret_cast<__half2*>(Chi + (size_t)r * ldc + col) =
                    __halves2half2(__float2half_rn(v0), __float2half_rn(v1));
            }
        }
    }
}

// ---------------------------------------------------------------------------
// 7) GEMM2: h2 = lrelu(hmid @ W2^T + b2) -> fp32 + fused BN stats.
//    CTA 128x128, BK=32, 8 warps (4m x 2n), 4-stage ring (wait_group 2),
//    2 CTAs/SM.
// ---------------------------------------------------------------------------
#define ROWB 80
#define MATB (128 * ROWB)
#define STAGEB (2 * MATB)            // A + B = 20480
#define SM_A 0
#define SM_B MATB
#define G2_NSTG 4
#define G2_SMEM (G2_NSTG * STAGEB)   // 81920 -> 2 CTAs/SM

__global__ void __launch_bounds__(256, 2)
k_gemm2(const __half* __restrict__ Ah, const __half* __restrict__ Bh,
        const float* __restrict__ bias, float* __restrict__ Cf) {
    extern __shared__ char smem[];
    const uint32_t sb = smem_u32(smem);
    const int tid = threadIdx.x;
    const int wid = tid >> 5;
    const int lane = tid & 31;
    const int warp_m = wid & 3;
    const int warp_n = wid >> 2;
    const int m0 = blockIdx.y * 128;
    const int n0 = blockIdx.x * 128;
    const int M = NN, K = DHID, ldc = DOUT;

    float acc[2][8][4];
    #pragma unroll
    for (int a = 0; a < 2; a++)
        #pragma unroll
        for (int b = 0; b < 8; b++)
            #pragma unroll
            for (int c = 0; c < 4; c++) acc[a][b][c] = 0.f;

    const int nchunks = K >> 5;      // 16

    auto load_chunk = [&](int ch) {
        const int k0 = ch << 5;
        const uint32_t stg = sb + (ch % G2_NSTG) * STAGEB;
        #pragma unroll
        for (int it = 0; it < 2; it++) {
            int idx = tid + it * 256;
            int row = idx >> 2;
            int c = idx & 3;
            uint32_t soff = (uint32_t)(row * ROWB + c * 16);
            int gmr = m0 + row;
            cp_async16(stg + SM_A + soff, Ah + (size_t)gmr * K + k0 + c * 8, gmr < M);
            int gnr = n0 + row;
            cp_async16(stg + SM_B + soff, Bh + (size_t)gnr * K + k0 + c * 8, true);
        }
        cp_commit();
    };

    load_chunk(0);
    load_chunk(1);
    load_chunk(2);

    for (int ch = 0; ch < nchunks; ch++) {
        int remaining = nchunks - 1 - ch;
        if (remaining >= 2) cp_wait2();
        else if (remaining == 1) cp_wait1();
        else cp_wait0();
        __syncthreads();

        const uint32_t stg = sb + (ch % G2_NSTG) * STAGEB;
        const uint32_t lrow = (uint32_t)(lane & 15);
        const uint32_t lchk = (uint32_t)(lane >> 4);

        #pragma unroll
        for (int ks = 0; ks < 2; ks++) {
            uint32_t a_hi[2][4];
            #pragma unroll
            for (int mt = 0; mt < 2; mt++) {
                uint32_t r = (uint32_t)(warp_m * 32 + mt * 16) + lrow;
                ldsm_x4(a_hi[mt], stg + SM_A + r * ROWB + lchk * 16 + ks * 32);
            }
            #pragma unroll
            for (int np = 0; np < 4; np++) {
                uint32_t bh[4];
                uint32_t r = (uint32_t)(warp_n * 64 + np * 16) + lrow;
                ldsm_x4(bh, stg + SM_B + r * ROWB + lchk * 16 + ks * 32);
                uint32_t b0h[2] = {bh[0], bh[2]}, b1h[2] = {bh[1], bh[3]};
                #pragma unroll
                for (int mt = 0; mt < 2; mt++) {
                    hmma(acc[mt][2 * np],     a_hi[mt], b0h);
                    hmma(acc[mt][2 * np + 1], a_hi[mt], b1h);
                }
            }
        }
        // load(ch+3) writes stage (ch-1)%4, fully drained at this barrier.
        if (ch + 3 < nchunks) load_chunk(ch + 3);
    }

    // Epilogue: bias + lrelu + store + BN stats
    float scol[8][2];
    float qcol[8][2];
    #pragma unroll
    for (int nt = 0; nt < 8; nt++) {
        scol[nt][0] = scol[nt][1] = 0.f;
        qcol[nt][0] = qcol[nt][1] = 0.f;
    }

    #pragma unroll
    for (int mt = 0; mt < 2; mt++) {
        int row = m0 + warp_m * 32 + mt * 16 + (lane >> 2);
        #pragma unroll
        for (int nt = 0; nt < 8; nt++) {
            int col = n0 + warp_n * 64 + nt * 8 + 2 * (lane & 3);
            float bx = bias[col], by = bias[col + 1];
            #pragma unroll
            for (int h = 0; h < 2; h++) {
                int r = row + h * 8;
                if (r >= M) continue;
                float v0 = acc[mt][nt][2 * h + 0] + bx;
                float v1 = acc[mt][nt][2 * h + 1] + by;
                v0 = v0 > 0.f ? v0 : 0.01f * v0;
                v1 = v1 > 0.f ? v1 : 0.01f * v1;
                *reinterpret_cast<float2*>(Cf + (size_t)r * ldc + col) =
                    make_float2(v0, v1);
                scol[nt][0] += v0; qcol[nt][0] += v0 * v0;
                scol[nt][1] += v1; qcol[nt][1] += v1 * v1;
            }
        }
    }

    {
        float* sarr = reinterpret_cast<float*>(smem);
        float* qarr = sarr + 128;
        __syncthreads();
        if (tid < 128) { sarr[tid] = 0.f; qarr[tid] = 0.f; }
        __syncthreads();
        #pragma unroll
        for (int nt = 0; nt < 8; nt++) {
            float s0 = scol[nt][0], s1 = scol[nt][1];
            float q0 = qcol[nt][0], q1 = qcol[nt][1];
            #pragma unroll
            for (int o = 4; o < 32; o <<= 1) {
                s0 += __shfl_xor_sync(0xffffffffu, s0, o);
                s1 += __shfl_xor_sync(0xffffffffu, s1, o);
                q0 += __shfl_xor_sync(0xffffffffu, q0, o);
                q1 += __shfl_xor_sync(0xffffffffu, q1, o);
            }
            if (lane < 4) {
                int c = warp_n * 64 + nt * 8 + 2 * lane;
                atomicAdd(&sarr[c], s0);
                atomicAdd(&sarr[c + 1], s1);
                atomicAdd(&qarr[c], q0);
                atomicAdd(&qarr[c + 1], q1);
            }
        }
        __syncthreads();
        if (tid < 128) {
            atomicAdd(&g_sum[n0 + tid], sarr[tid]);
            atomicAdd(&g_sumsq[n0 + tid], qarr[tid]);
        }
    }
}

// ---------------------------------------------------------------------------
// 8) normalize with inline BN finalize
// ---------------------------------------------------------------------------
__global__ void __launch_bounds__(256) k_normalize(float* __restrict__ out,
                                                   const float* __restrict__ gamma,
                                                   const float* __restrict__ beta) {
    __shared__ float4 s_sc[DOUT / 4];
    __shared__ float4 s_sh[DOUT / 4];
    const int tid = threadIdx.x;
    if (tid < DOUT / 4) {
        const float invn = 1.0f / (float)NN;
        float4 sc, sh;
        #pragma unroll
        for (int k = 0; k < 4; k++) {
            int c = tid * 4 + k;
            float mean = g_sum[c] * invn;
            float var = g_sumsq[c] * invn - mean * mean;
            float rstd = rsqrtf(var + 1e-5f);
            float s = gamma[c] * rstd;
            (&sc.x)[k] = s;
            (&sh.x)[k] = beta[c] - mean * s;
        }
        s_sc[tid] = sc;
        s_sh[tid] = sh;
    }
    __syncthreads();

    int i = blockIdx.x * blockDim.x + tid;
    const int n4 = NN * DOUT / 4;
    if (i >= n4) return;
    int c4 = i & (DOUT / 4 - 1);
    float4 v = reinterpret_cast<const float4*>(g_h2)[i];
    float4 sc = s_sc[c4];
    float4 sh = s_sh[c4];
    v.x = v.x * sc.x + sh.x;
    v.y = v.y * sc.y + sh.y;
    v.z = v.z * sc.z + sh.z;
    v.w = v.w * sc.w + sh.w;
    reinterpret_cast<float4*>(out)[i] = v;
}

// ---------------------------------------------------------------------------
extern "C" void kernel_launch(void* const* d_in, const int* in_sizes, int n_in,
                              void* d_out, int out_size) {
    const float* x     = (const float*)d_in[0];
    const int*   ei    = (const int*)d_in[1];
    const float* W1    = (const float*)d_in[2];
    const float* b1    = (const float*)d_in[3];
    const float* W2    = (const float*)d_in[4];
    const float* b2    = (const float*)d_in[5];
    const float* gamma = (const float*)d_in[6];
    const float* beta  = (const float*)d_in[7];
    float* out = (float*)d_out;

    __half *xhi, *mhi, *w1hi, *w2hi;
    float* h2;
    cudaGetSymbolAddress((void**)&xhi, g_xhi);
    cudaGetSymbolAddress((void**)&mhi, g_mhi);
    cudaGetSymbolAddress((void**)&w1hi, g_w1hi);
    cudaGetSymbolAddress((void**)&w2hi, g_w2hi);
    cudaGetSymbolAddress((void**)&h2, g_h2);

    cudaFuncSetAttribute(k_gemm1,
                         cudaFuncAttributeMaxDynamicSharedMemorySize, G1_SMEM);
    cudaFuncSetAttribute(k_gemm2,
                         cudaFuncAttributeMaxDynamicSharedMemorySize, G2_SMEM);

    // CSR build + fp16 convert + aggregate
    k_zero<<<(NN + 255) / 256, 256>>>();
    k_x2h<<<(NN * DIN / 4 + 255) / 256, 256>>>(x);
    k_hist<<<(NE + 255) / 256, 256>>>(ei);
    k_scan<<<1, 1024>>>();
    k_bucket<<<(NE + 255) / 256, 256>>>(ei);
    k_agg<<<(NN * 32 + 255) / 256, 256>>>();

    // weight prep
    k_prep_w<<<(DIN * DHID + 255) / 256, 256>>>(W1, w1hi, DIN, DHID);
    k_prep_w<<<(DHID * DOUT + 255) / 256, 256>>>(W2, w2hi, DHID, DOUT);

    // GEMM1: [50000x128]@[128x512] -> fp16 (single-shot K)
    {
        dim3 grid(DHID / 128, (NN + 127) / 128);
        k_gemm1<<<grid, 256, G1_SMEM>>>(xhi, w1hi, b1, mhi);
    }
    // GEMM2: [50000x512]@[512x256] -> fp32 (+fused BN stats)
    {
        dim3 grid(DOUT / 128, (NN + 127) / 128);
        k_gemm2<<<grid, 256, G2_SMEM>>>(mhi, w2hi, b2, h2);
    }
    // normalize (inline BN finalize)
    k_normalize<<<(NN * DOUT / 4 + 255) / 256, 256>>>(out, gamma, beta);
}

// round 12
// speedup vs baseline: 1.4548x; 1.4548x over previous
#include <cuda_runtime.h>
#include <cuda_fp16.h>
#include <cstdint>
#include <cstddef>

#define NN 50000
#define NE 800000
#define DIN 128
#define DHID 512
#define DOUT 256
#define SCAN_NB ((NN + 255) / 256)   // 196

// ---------------------------------------------------------------------------
// Scratch (device globals — no runtime allocation)
// ---------------------------------------------------------------------------
__device__ __half g_xhi[(size_t)NN * DIN];       // (x+agg) fp16
__device__ __half g_mhi[(size_t)NN * DHID];      // hmid fp16
__device__ float g_h2[(size_t)NN * DOUT];        // after layer2+act (fp32)
__device__ __half g_w1hi[(size_t)DHID * DIN];    // W1^T [N][K] fp16
__device__ __half g_w2hi[(size_t)DOUT * DHID];   // W2^T [N][K] fp16
__device__ float g_sum[DOUT];
__device__ float g_sumsq[DOUT];
// CSR build
__device__ int g_deg[NN];
__device__ int g_off[NN + 1];
__device__ int g_cur[NN];
__device__ int g_srcs[NE];
__device__ int g_blk[SCAN_NB];
__device__ int g_blkoff[SCAN_NB];

// ---------------------------------------------------------------------------
// PTX helpers
// ---------------------------------------------------------------------------
__device__ __forceinline__ uint32_t smem_u32(const void* p) {
    uint32_t a;
    asm("{ .reg .u64 t; cvta.to.shared.u64 t, %1; cvt.u32.u64 %0, t; }"
        : "=r"(a) : "l"(p));
    return a;
}
__device__ __forceinline__ void cp_async16(uint32_t dst, const void* src, bool pred) {
    int sz = pred ? 16 : 0;
    asm volatile("cp.async.cg.shared.global [%0], [%1], 16, %2;"
                 :: "r"(dst), "l"(src), "r"(sz));
}
__device__ __forceinline__ void cp_commit() {
    asm volatile("cp.async.commit_group;" ::: "memory");
}
__device__ __forceinline__ void cp_wait0() {
    asm volatile("cp.async.wait_group 0;" ::: "memory");
}
__device__ __forceinline__ void cp_wait1() {
    asm volatile("cp.async.wait_group 1;" ::: "memory");
}
__device__ __forceinline__ void ldsm_x4(uint32_t* r, uint32_t addr) {
    asm volatile("ldmatrix.sync.aligned.m8n8.x4.shared.b16 {%0,%1,%2,%3}, [%4];"
                 : "=r"(r[0]), "=r"(r[1]), "=r"(r[2]), "=r"(r[3]) : "r"(addr));
}
__device__ __forceinline__ void hmma(float* c, const uint32_t* a, const uint32_t* b) {
    asm volatile(
        "mma.sync.aligned.m16n8k16.row.col.f32.f16.f16.f32 "
        "{%0,%1,%2,%3}, {%4,%5,%6,%7}, {%8,%9}, {%0,%1,%2,%3};"
        : "+f"(c[0]), "+f"(c[1]), "+f"(c[2]), "+f"(c[3])
        : "r"(a[0]), "r"(a[1]), "r"(a[2]), "r"(a[3]), "r"(b[0]), "r"(b[1]));
}

// ---------------------------------------------------------------------------
// 0) zero: degree counters + BN accumulators
// ---------------------------------------------------------------------------
__global__ void k_zero() {
    int i = blockIdx.x * blockDim.x + threadIdx.x;
    if (i < NN) g_deg[i] = 0;
    if (i < DOUT) { g_sum[i] = 0.f; g_sumsq[i] = 0.f; }
}

// ---------------------------------------------------------------------------
// 1) histogram of dst degrees
// ---------------------------------------------------------------------------
__global__ void k_hist(const int* __restrict__ ei) {
    int e = blockIdx.x * blockDim.x + threadIdx.x;
    if (e < NE) atomicAdd(&g_deg[ei[NE + e]], 1);
}

// ---------------------------------------------------------------------------
// 2) parallel exclusive scan, 3 phases
// ---------------------------------------------------------------------------
__global__ void __launch_bounds__(256) k_scan1() {
    __shared__ int s[256];
    int i = blockIdx.x * 256 + threadIdx.x;
    int v = (i < NN) ? g_deg[i] : 0;
    s[threadIdx.x] = v;
    __syncthreads();
    #pragma unroll
    for (int d = 128; d > 0; d >>= 1) {
        if (threadIdx.x < d) s[threadIdx.x] += s[threadIdx.x + d];
        __syncthreads();
    }
    if (threadIdx.x == 0) g_blk[blockIdx.x] = s[0];
}

__global__ void __launch_bounds__(256) k_scan2() {
    __shared__ int s[256];
    int t = threadIdx.x;
    int v = (t < SCAN_NB) ? g_blk[t] : 0;
    s[t] = v;
    __syncthreads();
    // Hillis-Steele inclusive
    #pragma unroll
    for (int d = 1; d < 256; d <<= 1) {
        int u = (t >= d) ? s[t - d] : 0;
        __syncthreads();
        s[t] += u;
        __syncthreads();
    }
    if (t < SCAN_NB) g_blkoff[t] = s[t] - v;   // exclusive
    if (t == 0) g_off[NN] = NE;
}

__global__ void __launch_bounds__(256) k_scan3() {
    __shared__ int s[256];
    int t = threadIdx.x;
    int i = blockIdx.x * 256 + t;
    int v = (i < NN) ? g_deg[i] : 0;
    s[t] = v;
    __syncthreads();
    #pragma unroll
    for (int d = 1; d < 256; d <<= 1) {
        int u = (t >= d) ? s[t - d] : 0;
        __syncthreads();
        s[t] += u;
        __syncthreads();
    }
    if (i < NN) {
        int off = g_blkoff[blockIdx.x] + s[t] - v;   // exclusive prefix
        g_off[i] = off;
        g_cur[i] = off;
    }
}

// ---------------------------------------------------------------------------
// 3) bucket edges by dst
// ---------------------------------------------------------------------------
__global__ void k_bucket(const int* __restrict__ ei) {
    int e = blockIdx.x * blockDim.x + threadIdx.x;
    if (e >= NE) return;
    int dst = ei[NE + e];
    int pos = atomicAdd(&g_cur[dst], 1);
    g_srcs[pos] = ei[e];
}

// ---------------------------------------------------------------------------
// 4) aggregate: one warp per node; fp32 gather, fp16 out
// ---------------------------------------------------------------------------
__global__ void __launch_bounds__(256) k_agg(const float* __restrict__ x) {
    int w = (blockIdx.x * blockDim.x + threadIdx.x) >> 5;
    if (w >= NN) return;
    int lane = threadIdx.x & 31;

    float4 acc = reinterpret_cast<const float4*>(x + (size_t)w * DIN)[lane];
    int beg = g_off[w], end = g_off[w + 1];
    for (int base = beg; base < end; base += 32) {
        int n = end - base;
        if (n > 32) n = 32;
        int s = (lane < n) ? g_srcs[base + lane] : 0;
        #pragma unroll 4
        for (int j = 0; j < n; j++) {
            int src = __shfl_sync(0xffffffffu, s, j);
            float4 v = reinterpret_cast<const float4*>(x + (size_t)src * DIN)[lane];
            acc.x += v.x; acc.y += v.y; acc.z += v.z; acc.w += v.w;
        }
    }
    __half2* o = reinterpret_cast<__half2*>(g_xhi + (size_t)w * DIN + lane * 4);
    o[0] = __halves2half2(__float2half_rn(acc.x), __float2half_rn(acc.y));
    o[1] = __halves2half2(__float2half_rn(acc.z), __float2half_rn(acc.w));
}

// ---------------------------------------------------------------------------
// 5) W [K,N] -> W^T [N,K] fp16
// ---------------------------------------------------------------------------
__global__ void k_prep_w(const float* __restrict__ W, __half* __restrict__ hi,
                         int K, int N) {
    int i = blockIdx.x * blockDim.x + threadIdx.x;
    if (i >= K * N) return;
    int n = i / K, k = i % K;
    hi[i] = __float2half_rn(W[(size_t)k * N + n]);
}

// ---------------------------------------------------------------------------
// 6) GEMM1 single-shot: hmid = lrelu(A @ W1^T + b1) -> fp16.
//    K=128 loaded in one cp.async wave. CTA 128x128, 8 warps (4m x 2n),
//    2 CTAs/SM. Row pad 256B->272B (68 words = 4 mod 32, conflict-free ldsm).
// ---------------------------------------------------------------------------
#define A1_ROWB 272
#define A1_SZ (128 * A1_ROWB)        // 34816
#define G1_A 0
#define G1_B A1_SZ
#define G1_SMEM (2 * A1_SZ)          // 69632 -> 2 CTAs/SM

__global__ void __launch_bounds__(256, 2)
k_gemm1(const __half* __restrict__ Ah, const __half* __restrict__ Bh,
        const float* __restrict__ bias, __half* __restrict__ Chi) {
    extern __shared__ char smem[];
    const uint32_t sb = smem_u32(smem);
    const int tid = threadIdx.x;
    const int wid = tid >> 5;
    const int lane = tid & 31;
    const int warp_m = wid & 3;
    const int warp_n = wid >> 2;
    const int m0 = blockIdx.y * 128;
    const int n0 = blockIdx.x * 128;
    const int M = NN, K = DIN, ldc = DHID;

    #pragma unroll
    for (int it = 0; it < 8; it++) {
        int idx = tid + it * 256;            // 0..2047
        int row = idx >> 4;                  // 0..127
        int c = idx & 15;                    // 16B chunk within 256B row
        uint32_t soff = (uint32_t)(row * A1_ROWB + c * 16);
        int gmr = m0 + row;
        cp_async16(sb + G1_A + soff, Ah + (size_t)gmr * K + c * 8, gmr < M);
        int gnr = n0 + row;
        cp_async16(sb + G1_B + soff, Bh + (size_t)gnr * K + c * 8, true);
    }
    cp_commit();
    cp_wait0();
    __syncthreads();

    float acc[2][8][4];
    #pragma unroll
    for (int a = 0; a < 2; a++)
        #pragma unroll
        for (int b = 0; b < 8; b++)
            #pragma unroll
            for (int c = 0; c < 4; c++) acc[a][b][c] = 0.f;

    const uint32_t lrow = (uint32_t)(lane & 15);
    const uint32_t lchk = (uint32_t)(lane >> 4);

    #pragma unroll
    for (int ks = 0; ks < 8; ks++) {
        uint32_t a_hi[2][4];
        #pragma unroll
        for (int mt = 0; mt < 2; mt++) {
            uint32_t r = (uint32_t)(warp_m * 32 + mt * 16) + lrow;
            ldsm_x4(a_hi[mt], sb + G1_A + r * A1_ROWB + lchk * 16 + ks * 32);
        }
        #pragma unroll
        for (int np = 0; np < 4; np++) {
            uint32_t bh[4];
            uint32_t r = (uint32_t)(warp_n * 64 + np * 16) + lrow;
            ldsm_x4(bh, sb + G1_B + r * A1_ROWB + lchk * 16 + ks * 32);
            uint32_t b0h[2] = {bh[0], bh[2]}, b1h[2] = {bh[1], bh[3]};
            #pragma unroll
            for (int mt = 0; mt < 2; mt++) {
                hmma(acc[mt][2 * np],     a_hi[mt], b0h);
                hmma(acc[mt][2 * np + 1], a_hi[mt], b1h);
            }
        }
    }

    #pragma unroll
    for (int mt = 0; mt < 2; mt++) {
        int row = m0 + warp_m * 32 + mt * 16 + (lane >> 2);
        #pragma unroll
        for (int nt = 0; nt < 8; nt++) {
            int col = n0 + warp_n * 64 + nt * 8 + 2 * (lane & 3);
            float bx = bias[col], by = bias[col + 1];
            #pragma unroll
            for (int h = 0; h < 2; h++) {
                int r = row + h * 8;
                if (r >= M) continue;
                float v0 = acc[mt][nt][2 * h + 0] + bx;
                float v1 = acc[mt][nt][2 * h + 1] + by;
                v0 = v0 > 0.f ? v0 : 0.01f * v0;
                v1 = v1 > 0.f ? v1 : 0.01f * v1;
                *reinterpret_cast<__half2*>(Chi + (size_t)r * ldc + col) =
                    __halves2half2(__float2half_rn(v0), __float2half_rn(v1));
            }
        }
    }
}

// ---------------------------------------------------------------------------
// 7) GEMM2: h2 = lrelu(hmid @ W2^T + b2) -> fp32 + fused BN stats.
//    CTA 128x128, BK=32, 8 warps (4m x 2n), 3-stage ring, 2 CTAs/SM.
// ---------------------------------------------------------------------------
#define ROWB 80
#define MATB (128 * ROWB)
#define STAGEB (2 * MATB)            // A + B = 20480
#define SM_A 0
#define SM_B MATB
#define G2_SMEM (3 * STAGEB)         // 61440 -> 2 CTAs/SM

__global__ void __launch_bounds__(256, 2)
k_gemm2(const __half* __restrict__ Ah, const __half* __restrict__ Bh,
        const float* __restrict__ bias, float* __restrict__ Cf) {
    extern __shared__ char smem[];
    const uint32_t sb = smem_u32(smem);
    const int tid = threadIdx.x;
    const int wid = tid >> 5;
    const int lane = tid & 31;
    const int warp_m = wid & 3;
    const int warp_n = wid >> 2;
    const int m0 = blockIdx.y * 128;
    const int n0 = blockIdx.x * 128;
    const int M = NN, K = DHID, ldc = DOUT;

    float acc[2][8][4];
    #pragma unroll
    for (int a = 0; a < 2; a++)
        #pragma unroll
        for (int b = 0; b < 8; b++)
            #pragma unroll
            for (int c = 0; c < 4; c++) acc[a][b][c] = 0.f;

    const int nchunks = K >> 5;

    auto load_chunk = [&](int ch) {
        const int k0 = ch << 5;
        const uint32_t stg = sb + (ch % 3) * STAGEB;
        #pragma unroll
        for (int it = 0; it < 2; it++) {
            int idx = tid + it * 256;
            int row = idx >> 2;
            int c = idx & 3;
            uint32_t soff = (uint32_t)(row * ROWB + c * 16);
            int gmr = m0 + row;
            cp_async16(stg + SM_A + soff, Ah + (size_t)gmr * K + k0 + c * 8, gmr < M);
            int gnr = n0 + row;
            cp_async16(stg + SM_B + soff, Bh + (size_t)gnr * K + k0 + c * 8, true);
        }
        cp_commit();
    };

    load_chunk(0);
    load_chunk(1);

    for (int ch = 0; ch < nchunks; ch++) {
        if (ch + 1 < nchunks) cp_wait1(); else cp_wait0();
        __syncthreads();

        const uint32_t stg = sb + (ch % 3) * STAGEB;
        const uint32_t lrow = (uint32_t)(lane & 15);
        const uint32_t lchk = (uint32_t)(lane >> 4);

        #pragma unroll
        for (int ks = 0; ks < 2; ks++) {
            uint32_t a_hi[2][4];
            #pragma unroll
            for (int mt = 0; mt < 2; mt++) {
                uint32_t r = (uint32_t)(warp_m * 32 + mt * 16) + lrow;
                ldsm_x4(a_hi[mt], stg + SM_A + r * ROWB + lchk * 16 + ks * 32);
            }
            #pragma unroll
            for (int np = 0; np < 4; np++) {
                uint32_t bh[4];
                uint32_t r = (uint32_t)(warp_n * 64 + np * 16) + lrow;
                ldsm_x4(bh, stg + SM_B + r * ROWB + lchk * 16 + ks * 32);
                uint32_t b0h[2] = {bh[0], bh[2]}, b1h[2] = {bh[1], bh[3]};
                #pragma unroll
                for (int mt = 0; mt < 2; mt++) {
                    hmma(acc[mt][2 * np],     a_hi[mt], b0h);
                    hmma(acc[mt][2 * np + 1], a_hi[mt], b1h);
                }
            }
        }
        if (ch + 2 < nchunks) load_chunk(ch + 2);
    }

    // Epilogue: bias + lrelu + store + BN stats
    float scol[8][2];
    float qcol[8][2];
    #pragma unroll
    for (int nt = 0; nt < 8; nt++) {
        scol[nt][0] = scol[nt][1] = 0.f;
        qcol[nt][0] = qcol[nt][1] = 0.f;
    }

    #pragma unroll
    for (int mt = 0; mt < 2; mt++) {
        int row = m0 + warp_m * 32 + mt * 16 + (lane >> 2);
        #pragma unroll
        for (int nt = 0; nt < 8; nt++) {
            int col = n0 + warp_n * 64 + nt * 8 + 2 * (lane & 3);
            float bx = bias[col], by = bias[col + 1];
            #pragma unroll
            for (int h = 0; h < 2; h++) {
                int r = row + h * 8;
                if (r >= M) continue;
                float v0 = acc[mt][nt][2 * h + 0] + bx;
                float v1 = acc[mt][nt][2 * h + 1] + by;
                v0 = v0 > 0.f ? v0 : 0.01f * v0;
                v1 = v1 > 0.f ? v1 : 0.01f * v1;
                *reinterpret_cast<float2*>(Cf + (size_t)r * ldc + col) =
                    make_float2(v0, v1);
                scol[nt][0] += v0; qcol[nt][0] += v0 * v0;
                scol[nt][1] += v1; qcol[nt][1] += v1 * v1;
            }
        }
    }

    {
        float* sarr = reinterpret_cast<float*>(smem);
        float* qarr = sarr + 128;
        __syncthreads();
        if (tid < 128) { sarr[tid] = 0.f; qarr[tid] = 0.f; }
        __syncthreads();
        #pragma unroll
        for (int nt = 0; nt < 8; nt++) {
            float s0 = scol[nt][0], s1 = scol[nt][1];
            float q0 = qcol[nt][0], q1 = qcol[nt][1];
            #pragma unroll
            for (int o = 4; o < 32; o <<= 1) {
                s0 += __shfl_xor_sync(0xffffffffu, s0, o);
                s1 += __shfl_xor_sync(0xffffffffu, s1, o);
                q0 += __shfl_xor_sync(0xffffffffu, q0, o);
                q1 += __shfl_xor_sync(0xffffffffu, q1, o);
            }
            if (lane < 4) {
                int c = warp_n * 64 + nt * 8 + 2 * lane;
                atomicAdd(&sarr[c], s0);
                atomicAdd(&sarr[c + 1], s1);
                atomicAdd(&qarr[c], q0);
                atomicAdd(&qarr[c + 1], q1);
            }
        }
        __syncthreads();
        if (tid < 128) {
            atomicAdd(&g_sum[n0 + tid], sarr[tid]);
            atomicAdd(&g_sumsq[n0 + tid], qarr[tid]);
        }
    }
}

// ---------------------------------------------------------------------------
// 8) normalize with inline BN finalize
// ---------------------------------------------------------------------------
__global__ void __launch_bounds__(256) k_normalize(float* __restrict__ out,
                                                   const float* __restrict__ gamma,
                                                   const float* __restrict__ beta) {
    __shared__ float4 s_sc[DOUT / 4];
    __shared__ float4 s_sh[DOUT / 4];
    const int tid = threadIdx.x;
    if (tid < DOUT / 4) {
        const float invn = 1.0f / (float)NN;
        float4 sc, sh;
        #pragma unroll
        for (int k = 0; k < 4; k++) {
            int c = tid * 4 + k;
            float mean = g_sum[c] * invn;
            float var = g_sumsq[c] * invn - mean * mean;
            float rstd = rsqrtf(var + 1e-5f);
            float s = gamma[c] * rstd;
            (&sc.x)[k] = s;
            (&sh.x)[k] = beta[c] - mean * s;
        }
        s_sc[tid] = sc;
        s_sh[tid] = sh;
    }
    __syncthreads();

    int i = blockIdx.x * blockDim.x + tid;
    const int n4 = NN * DOUT / 4;
    if (i >= n4) return;
    int c4 = i & (DOUT / 4 - 1);
    float4 v = reinterpret_cast<const float4*>(g_h2)[i];
    float4 sc = s_sc[c4];
    float4 sh = s_sh[c4];
    v.x = v.x * sc.x + sh.x;
    v.y = v.y * sc.y + sh.y;
    v.z = v.z * sc.z + sh.z;
    v.w = v.w * sc.w + sh.w;
    reinterpret_cast<float4*>(out)[i] = v;
}

// ---------------------------------------------------------------------------
extern "C" void kernel_launch(void* const* d_in, const int* in_sizes, int n_in,
                              void* d_out, int out_size) {
    const float* x     = (const float*)d_in[0];
    const int*   ei    = (const int*)d_in[1];
    const float* W1    = (const float*)d_in[2];
    const float* b1    = (const float*)d_in[3];
    const float* W2    = (const float*)d_in[4];
    const float* b2    = (const float*)d_in[5];
    const float* gamma = (const float*)d_in[6];
    const float* beta  = (const float*)d_in[7];
    float* out = (float*)d_out;

    __half *xhi, *mhi, *w1hi, *w2hi;
    float* h2;
    cudaGetSymbolAddress((void**)&xhi, g_xhi);
    cudaGetSymbolAddress((void**)&mhi, g_mhi);
    cudaGetSymbolAddress((void**)&w1hi, g_w1hi);
    cudaGetSymbolAddress((void**)&w2hi, g_w2hi);
    cudaGetSymbolAddress((void**)&h2, g_h2);

    cudaFuncSetAttribute(k_gemm1,
                         cudaFuncAttributeMaxDynamicSharedMemorySize, G1_SMEM);
    cudaFuncSetAttribute(k_gemm2,
                         cudaFuncAttributeMaxDynamicSharedMemorySize, G2_SMEM);

    // CSR build + aggregate (+fp16 convert)
    k_zero<<<(NN + 255) / 256, 256>>>();
    k_hist<<<(NE + 255) / 256, 256>>>(ei);
    k_scan1<<<SCAN_NB, 256>>>();
    k_scan2<<<1, 256>>>();
    k_scan3<<<SCAN_NB, 256>>>();
    k_bucket<<<(NE + 255) / 256, 256>>>(ei);
    k_agg<<<(NN * 32 + 255) / 256, 256>>>(x);

    // weight prep
    k_prep_w<<<(DIN * DHID + 255) / 256, 256>>>(W1, w1hi, DIN, DHID);
    k_prep_w<<<(DHID * DOUT + 255) / 256, 256>>>(W2, w2hi, DHID, DOUT);

    // GEMM1: [50000x128]@[128x512] -> fp16 (single-shot K)
    {
        dim3 grid(DHID / 128, (NN + 127) / 128);
        k_gemm1<<<grid, 256, G1_SMEM>>>(xhi, w1hi, b1, mhi);
    }
    // GEMM2: [50000x512]@[512x256] -> fp32 (+fused BN stats)
    {
        dim3 grid(DOUT / 128, (NN + 127) / 128);
        k_gemm2<<<grid, 256, G2_SMEM>>>(mhi, w2hi, b2, h2);
    }
    // normalize (inline BN finalize)
    k_normalize<<<(NN * DOUT / 4 + 255) / 256, 256>>>(out, gamma, beta);
}

// round 13
// speedup vs baseline: 1.4677x; 1.0089x over previous
#include <cuda_runtime.h>
#include <cuda_fp16.h>
#include <cstdint>
#include <cstddef>

#define NN 50000
#define NE 800000
#define DIN 128
#define DHID 512
#define DOUT 256
#define SCAN_NB ((NN + 255) / 256)   // 196

// ---------------------------------------------------------------------------
// Scratch (device globals — no runtime allocation)
// ---------------------------------------------------------------------------
__device__ __half g_xh[(size_t)NN * DIN];        // x fp16 (gather source)
__device__ __half g_xhi[(size_t)NN * DIN];       // (x+agg) fp16
__device__ __half g_mhi[(size_t)NN * DHID];      // hmid fp16
__device__ __half g_h2[(size_t)NN * DOUT];       // after layer2+act (fp16)
__device__ __half g_w1hi[(size_t)DHID * DIN];    // W1^T [N][K] fp16
__device__ __half g_w2hi[(size_t)DOUT * DHID];   // W2^T [N][K] fp16
__device__ float g_sum[DOUT];
__device__ float g_sumsq[DOUT];
// CSR build
__device__ int g_deg[NN];
__device__ int g_off[NN + 1];
__device__ int g_cur[NN];
__device__ int g_srcs[NE];
__device__ int g_blk[SCAN_NB];
__device__ int g_blkoff[SCAN_NB];

// ---------------------------------------------------------------------------
// PTX helpers
// ---------------------------------------------------------------------------
__device__ __forceinline__ uint32_t smem_u32(const void* p) {
    uint32_t a;
    asm("{ .reg .u64 t; cvta.to.shared.u64 t, %1; cvt.u32.u64 %0, t; }"
        : "=r"(a) : "l"(p));
    return a;
}
__device__ __forceinline__ void cp_async16(uint32_t dst, const void* src, bool pred) {
    int sz = pred ? 16 : 0;
    asm volatile("cp.async.cg.shared.global [%0], [%1], 16, %2;"
                 :: "r"(dst), "l"(src), "r"(sz));
}
__device__ __forceinline__ void cp_commit() {
    asm volatile("cp.async.commit_group;" ::: "memory");
}
__device__ __forceinline__ void cp_wait0() {
    asm volatile("cp.async.wait_group 0;" ::: "memory");
}
__device__ __forceinline__ void cp_wait1() {
    asm volatile("cp.async.wait_group 1;" ::: "memory");
}
__device__ __forceinline__ void ldsm_x4(uint32_t* r, uint32_t addr) {
    asm volatile("ldmatrix.sync.aligned.m8n8.x4.shared.b16 {%0,%1,%2,%3}, [%4];"
                 : "=r"(r[0]), "=r"(r[1]), "=r"(r[2]), "=r"(r[3]) : "r"(addr));
}
__device__ __forceinline__ void hmma(float* c, const uint32_t* a, const uint32_t* b) {
    asm volatile(
        "mma.sync.aligned.m16n8k16.row.col.f32.f16.f16.f32 "
        "{%0,%1,%2,%3}, {%4,%5,%6,%7}, {%8,%9}, {%0,%1,%2,%3};"
        : "+f"(c[0]), "+f"(c[1]), "+f"(c[2]), "+f"(c[3])
        : "r"(a[0]), "r"(a[1]), "r"(a[2]), "r"(a[3]), "r"(b[0]), "r"(b[1]));
}

// ---------------------------------------------------------------------------
// 0) zero degree/BN accumulators + convert x -> fp16 (one fused launch)
// ---------------------------------------------------------------------------
__global__ void k_zero_x2h(const float* __restrict__ x) {
    int i = blockIdx.x * blockDim.x + threadIdx.x;
    if (i < NN) g_deg[i] = 0;
    if (i < DOUT) { g_sum[i] = 0.f; g_sumsq[i] = 0.f; }
    const int n4 = NN * DIN / 4;
    if (i < n4) {
        float4 v = reinterpret_cast<const float4*>(x)[i];
        __half2* o = reinterpret_cast<__half2*>(g_xh) + i * 2;
        o[0] = __halves2half2(__float2half_rn(v.x), __float2half_rn(v.y));
        o[1] = __halves2half2(__float2half_rn(v.z), __float2half_rn(v.w));
    }
}

// ---------------------------------------------------------------------------
// 1) histogram of dst degrees
// ---------------------------------------------------------------------------
__global__ void k_hist(const int* __restrict__ ei) {
    int e = blockIdx.x * blockDim.x + threadIdx.x;
    if (e < NE) atomicAdd(&g_deg[ei[NE + e]], 1);
}

// ---------------------------------------------------------------------------
// 2) parallel exclusive scan, 3 phases
// ---------------------------------------------------------------------------
__global__ void __launch_bounds__(256) k_scan1() {
    __shared__ int s[256];
    int i = blockIdx.x * 256 + threadIdx.x;
    int v = (i < NN) ? g_deg[i] : 0;
    s[threadIdx.x] = v;
    __syncthreads();
    #pragma unroll
    for (int d = 128; d > 0; d >>= 1) {
        if (threadIdx.x < d) s[threadIdx.x] += s[threadIdx.x + d];
        __syncthreads();
    }
    if (threadIdx.x == 0) g_blk[blockIdx.x] = s[0];
}

__global__ void __launch_bounds__(256) k_scan2() {
    __shared__ int s[256];
    int t = threadIdx.x;
    int v = (t < SCAN_NB) ? g_blk[t] : 0;
    s[t] = v;
    __syncthreads();
    #pragma unroll
    for (int d = 1; d < 256; d <<= 1) {
        int u = (t >= d) ? s[t - d] : 0;
        __syncthreads();
        s[t] += u;
        __syncthreads();
    }
    if (t < SCAN_NB) g_blkoff[t] = s[t] - v;
    if (t == 0) g_off[NN] = NE;
}

__global__ void __launch_bounds__(256) k_scan3() {
    __shared__ int s[256];
    int t = threadIdx.x;
    int i = blockIdx.x * 256 + t;
    int v = (i < NN) ? g_deg[i] : 0;
    s[t] = v;
    __syncthreads();
    #pragma unroll
    for (int d = 1; d < 256; d <<= 1) {
        int u = (t >= d) ? s[t - d] : 0;
        __syncthreads();
        s[t] += u;
        __syncthreads();
    }
    if (i < NN) {
        int off = g_blkoff[blockIdx.x] + s[t] - v;
        g_off[i] = off;
        g_cur[i] = off;
    }
}

// ---------------------------------------------------------------------------
// 3) bucket edges by dst
// ---------------------------------------------------------------------------
__global__ void k_bucket(const int* __restrict__ ei) {
    int e = blockIdx.x * blockDim.x + threadIdx.x;
    if (e >= NE) return;
    int dst = ei[NE + e];
    int pos = atomicAdd(&g_cur[dst], 1);
    g_srcs[pos] = ei[e];
}

// ---------------------------------------------------------------------------
// 4) aggregate: one warp per node; fp16 gather, fp32 accumulate, fp16 out
// ---------------------------------------------------------------------------
__global__ void __launch_bounds__(256) k_agg() {
    int w = (blockIdx.x * blockDim.x + threadIdx.x) >> 5;
    if (w >= NN) return;
    int lane = threadIdx.x & 31;

    float acc0, acc1, acc2, acc3;
    {
        uint2 v = *reinterpret_cast<const uint2*>(g_xh + (size_t)w * DIN + lane * 4);
        float2 f0 = __half22float2(*reinterpret_cast<__half2*>(&v.x));
        float2 f1 = __half22float2(*reinterpret_cast<__half2*>(&v.y));
        acc0 = f0.x; acc1 = f0.y; acc2 = f1.x; acc3 = f1.y;
    }
    int beg = g_off[w], end = g_off[w + 1];
    for (int base = beg; base < end; base += 32) {
        int n = end - base;
        if (n > 32) n = 32;
        int s = (lane < n) ? g_srcs[base + lane] : 0;
        #pragma unroll 4
        for (int j = 0; j < n; j++) {
            int src = __shfl_sync(0xffffffffu, s, j);
            uint2 v = *reinterpret_cast<const uint2*>(g_xh + (size_t)src * DIN + lane * 4);
            float2 f0 = __half22float2(*reinterpret_cast<__half2*>(&v.x));
            float2 f1 = __half22float2(*reinterpret_cast<__half2*>(&v.y));
            acc0 += f0.x; acc1 += f0.y; acc2 += f1.x; acc3 += f1.y;
        }
    }
    __half2* o = reinterpret_cast<__half2*>(g_xhi + (size_t)w * DIN + lane * 4);
    o[0] = __halves2half2(__float2half_rn(acc0), __float2half_rn(acc1));
    o[1] = __halves2half2(__float2half_rn(acc2), __float2half_rn(acc3));
}

// ---------------------------------------------------------------------------
// 5) W [K,N] -> W^T [N,K] fp16
// ---------------------------------------------------------------------------
__global__ void k_prep_w(const float* __restrict__ W, __half* __restrict__ hi,
                         int K, int N) {
    int i = blockIdx.x * blockDim.x + threadIdx.x;
    if (i >= K * N) return;
    int n = i / K, k = i % K;
    hi[i] = __float2half_rn(W[(size_t)k * N + n]);
}

// ---------------------------------------------------------------------------
// 6) GEMM1 single-shot: hmid = lrelu(A @ W1^T + b1) -> fp16.
//    K=128 loaded in one cp.async wave. CTA 128x128, 8 warps (4m x 2n),
//    2 CTAs/SM. Row pad 256B->272B (conflict-free ldsm).
// ---------------------------------------------------------------------------
#define A1_ROWB 272
#define A1_SZ (128 * A1_ROWB)        // 34816
#define G1_A 0
#define G1_B A1_SZ
#define G1_SMEM (2 * A1_SZ)          // 69632 -> 2 CTAs/SM

__global__ void __launch_bounds__(256, 2)
k_gemm1(const __half* __restrict__ Ah, const __half* __restrict__ Bh,
        const float* __restrict__ bias, __half* __restrict__ Chi) {
    extern __shared__ char smem[];
    const uint32_t sb = smem_u32(smem);
    const int tid = threadIdx.x;
    const int wid = tid >> 5;
    const int lane = tid & 31;
    const int warp_m = wid & 3;
    const int warp_n = wid >> 2;
    const int m0 = blockIdx.y * 128;
    const int n0 = blockIdx.x * 128;
    const int M = NN, K = DIN, ldc = DHID;

    #pragma unroll
    for (int it = 0; it < 8; it++) {
        int idx = tid + it * 256;
        int row = idx >> 4;
        int c = idx & 15;
        uint32_t soff = (uint32_t)(row * A1_ROWB + c * 16);
        int gmr = m0 + row;
        cp_async16(sb + G1_A + soff, Ah + (size_t)gmr * K + c * 8, gmr < M);
        int gnr = n0 + row;
        cp_async16(sb + G1_B + soff, Bh + (size_t)gnr * K + c * 8, true);
    }
    cp_commit();
    cp_wait0();
    __syncthreads();

    float acc[2][8][4];
    #pragma unroll
    for (int a = 0; a < 2; a++)
        #pragma unroll
        for (int b = 0; b < 8; b++)
            #pragma unroll
            for (int c = 0; c < 4; c++) acc[a][b][c] = 0.f;

    const uint32_t lrow = (uint32_t)(lane & 15);
    const uint32_t lchk = (uint32_t)(lane >> 4);

    #pragma unroll
    for (int ks = 0; ks < 8; ks++) {
        uint32_t a_hi[2][4];
        #pragma unroll
        for (int mt = 0; mt < 2; mt++) {
            uint32_t r = (uint32_t)(warp_m * 32 + mt * 16) + lrow;
            ldsm_x4(a_hi[mt], sb + G1_A + r * A1_ROWB + lchk * 16 + ks * 32);
        }
        #pragma unroll
        for (int np = 0; np < 4; np++) {
            uint32_t bh[4];
            uint32_t r = (uint32_t)(warp_n * 64 + np * 16) + lrow;
            ldsm_x4(bh, sb + G1_B + r * A1_ROWB + lchk * 16 + ks * 32);
            uint32_t b0h[2] = {bh[0], bh[2]}, b1h[2] = {bh[1], bh[3]};
            #pragma unroll
            for (int mt = 0; mt < 2; mt++) {
                hmma(acc[mt][2 * np],     a_hi[mt], b0h);
                hmma(acc[mt][2 * np + 1], a_hi[mt], b1h);
            }
        }
    }

    #pragma unroll
    for (int mt = 0; mt < 2; mt++) {
        int row = m0 + warp_m * 32 + mt * 16 + (lane >> 2);
        #pragma unroll
        for (int nt = 0; nt < 8; nt++) {
            int col = n0 + warp_n * 64 + nt * 8 + 2 * (lane & 3);
            float bx = bias[col], by = bias[col + 1];
            #pragma unroll
            for (int h = 0; h < 2; h++) {
                int r = row + h * 8;
                if (r >= M) continue;
                float v0 = acc[mt][nt][2 * h + 0] + bx;
                float v1 = acc[mt][nt][2 * h + 1] + by;
                v0 = v0 > 0.f ? v0 : 0.01f * v0;
                v1 = v1 > 0.f ? v1 : 0.01f * v1;
                *reinterpret_cast<__half2*>(Chi + (size_t)r * ldc + col) =
                    __halves2half2(__float2half_rn(v0), __float2half_rn(v1));
            }
        }
    }
}

// ---------------------------------------------------------------------------
// 7) GEMM2: h2 = lrelu(hmid @ W2^T + b2) -> fp16 + fused BN stats (fp32).
//    CTA 128x128, BK=32, 8 warps (4m x 2n), 3-stage ring, 2 CTAs/SM.
// ---------------------------------------------------------------------------
#define ROWB 80
#define MATB (128 * ROWB)
#define STAGEB (2 * MATB)
#define SM_A 0
#define SM_B MATB
#define G2_SMEM (3 * STAGEB)         // 61440 -> 2 CTAs/SM

__global__ void __launch_bounds__(256, 2)
k_gemm2(const __half* __restrict__ Ah, const __half* __restrict__ Bh,
        const float* __restrict__ bias, __half* __restrict__ Ch) {
    extern __shared__ char smem[];
    const uint32_t sb = smem_u32(smem);
    const int tid = threadIdx.x;
    const int wid = tid >> 5;
    const int lane = tid & 31;
    const int warp_m = wid & 3;
    const int warp_n = wid >> 2;
    const int m0 = blockIdx.y * 128;
    const int n0 = blockIdx.x * 128;
    const int M = NN, K = DHID, ldc = DOUT;

    float acc[2][8][4];
    #pragma unroll
    for (int a = 0; a < 2; a++)
        #pragma unroll
        for (int b = 0; b < 8; b++)
            #pragma unroll
            for (int c = 0; c < 4; c++) acc[a][b][c] = 0.f;

    const int nchunks = K >> 5;

    auto load_chunk = [&](int ch) {
        const int k0 = ch << 5;
        const uint32_t stg = sb + (ch % 3) * STAGEB;
        #pragma unroll
        for (int it = 0; it < 2; it++) {
            int idx = tid + it * 256;
            int row = idx >> 2;
            int c = idx & 3;
            uint32_t soff = (uint32_t)(row * ROWB + c * 16);
            int gmr = m0 + row;
            cp_async16(stg + SM_A + soff, Ah + (size_t)gmr * K + k0 + c * 8, gmr < M);
            int gnr = n0 + row;
            cp_async16(stg + SM_B + soff, Bh + (size_t)gnr * K + k0 + c * 8, true);
        }
        cp_commit();
    };

    load_chunk(0);
    load_chunk(1);

    for (int ch = 0; ch < nchunks; ch++) {
        if (ch + 1 < nchunks) cp_wait1(); else cp_wait0();
        __syncthreads();

        const uint32_t stg = sb + (ch % 3) * STAGEB;
        const uint32_t lrow = (uint32_t)(lane & 15);
        const uint32_t lchk = (uint32_t)(lane >> 4);

        #pragma unroll
        for (int ks = 0; ks < 2; ks++) {
            uint32_t a_hi[2][4];
            #pragma unroll
            for (int mt = 0; mt < 2; mt++) {
                uint32_t r = (uint32_t)(warp_m * 32 + mt * 16) + lrow;
                ldsm_x4(a_hi[mt], stg + SM_A + r * ROWB + lchk * 16 + ks * 32);
            }
            #pragma unroll
            for (int np = 0; np < 4; np++) {
                uint32_t bh[4];
                uint32_t r = (uint32_t)(warp_n * 64 + np * 16) + lrow;
                ldsm_x4(bh, stg + SM_B + r * ROWB + lchk * 16 + ks * 32);
                uint32_t b0h[2] = {bh[0], bh[2]}, b1h[2] = {bh[1], bh[3]};
                #pragma unroll
                for (int mt = 0; mt < 2; mt++) {
                    hmma(acc[mt][2 * np],     a_hi[mt], b0h);
                    hmma(acc[mt][2 * np + 1], a_hi[mt], b1h);
                }
            }
        }
        if (ch + 2 < nchunks) load_chunk(ch + 2);
    }

    // Epilogue: bias + lrelu + fp16 store + fp32 BN stats
    float scol[8][2];
    float qcol[8][2];
    #pragma unroll
    for (int nt = 0; nt < 8; nt++) {
        scol[nt][0] = scol[nt][1] = 0.f;
        qcol[nt][0] = qcol[nt][1] = 0.f;
    }

    #pragma unroll
    for (int mt = 0; mt < 2; mt++) {
        int row = m0 + warp_m * 32 + mt * 16 + (lane >> 2);
        #pragma unroll
        for (int nt = 0; nt < 8; nt++) {
            int col = n0 + warp_n * 64 + nt * 8 + 2 * (lane & 3);
            float bx = bias[col], by = bias[col + 1];
            #pragma unroll
            for (int h = 0; h < 2; h++) {
                int r = row + h * 8;
                if (r >= M) continue;
                float v0 = acc[mt][nt][2 * h + 0] + bx;
                float v1 = acc[mt][nt][2 * h + 1] + by;
                v0 = v0 > 0.f ? v0 : 0.01f * v0;
                v1 = v1 > 0.f ? v1 : 0.01f * v1;
                *reinterpret_cast<__half2*>(Ch + (size_t)r * ldc + col) =
                    __halves2half2(__float2half_rn(v0), __float2half_rn(v1));
                scol[nt][0] += v0; qcol[nt][0] += v0 * v0;
                scol[nt][1] += v1; qcol[nt][1] += v1 * v1;
            }
        }
    }

    {
        float* sarr = reinterpret_cast<float*>(smem);
        float* qarr = sarr + 128;
        __syncthreads();
        if (tid < 128) { sarr[tid] = 0.f; qarr[tid] = 0.f; }
        __syncthreads();
        #pragma unroll
        for (int nt = 0; nt < 8; nt++) {
            float s0 = scol[nt][0], s1 = scol[nt][1];
            float q0 = qcol[nt][0], q1 = qcol[nt][1];
            #pragma unroll
            for (int o = 4; o < 32; o <<= 1) {
                s0 += __shfl_xor_sync(0xffffffffu, s0, o);
                s1 += __shfl_xor_sync(0xffffffffu, s1, o);
                q0 += __shfl_xor_sync(0xffffffffu, q0, o);
                q1 += __shfl_xor_sync(0xffffffffu, q1, o);
            }
            if (lane < 4) {
                int c = warp_n * 64 + nt * 8 + 2 * lane;
                atomicAdd(&sarr[c], s0);
                atomicAdd(&sarr[c + 1], s1);
                atomicAdd(&qarr[c], q0);
                atomicAdd(&qarr[c + 1], q1);
            }
        }
        __syncthreads();
        if (tid < 128) {
            atomicAdd(&g_sum[n0 + tid], sarr[tid]);
            atomicAdd(&g_sumsq[n0 + tid], qarr[tid]);
        }
    }
}

// ---------------------------------------------------------------------------
// 8) normalize with inline BN finalize (fp16 h2 in, fp32 out)
// ---------------------------------------------------------------------------
__global__ void __launch_bounds__(256) k_normalize(float* __restrict__ out,
                                                   const float* __restrict__ gamma,
                                                   const float* __restrict__ beta) {
    __shared__ float4 s_sc[DOUT / 4];
    __shared__ float4 s_sh[DOUT / 4];
    const int tid = threadIdx.x;
    if (tid < DOUT / 4) {
        const float invn = 1.0f / (float)NN;
        float4 sc, sh;
        #pragma unroll
        for (int k = 0; k < 4; k++) {
            int c = tid * 4 + k;
            float mean = g_sum[c] * invn;
            float var = g_sumsq[c] * invn - mean * mean;
            float rstd = rsqrtf(var + 1e-5f);
            float s = gamma[c] * rstd;
            (&sc.x)[k] = s;
            (&sh.x)[k] = beta[c] - mean * s;
        }
        s_sc[tid] = sc;
        s_sh[tid] = sh;
    }
    __syncthreads();

    int i = blockIdx.x * blockDim.x + tid;
    const int n4 = NN * DOUT / 4;
    if (i >= n4) return;
    int c4 = i & (DOUT / 4 - 1);
    uint2 hv = reinterpret_cast<const uint2*>(g_h2)[i];
    float2 f0 = __half22float2(*reinterpret_cast<__half2*>(&hv.x));
    float2 f1 = __half22float2(*reinterpret_cast<__half2*>(&hv.y));
    float4 sc = s_sc[c4];
    float4 sh = s_sh[c4];
    float4 v;
    v.x = f0.x * sc.x + sh.x;
    v.y = f0.y * sc.y + sh.y;
    v.z = f1.x * sc.z + sh.z;
    v.w = f1.y * sc.w + sh.w;
    reinterpret_cast<float4*>(out)[i] = v;
}

// ---------------------------------------------------------------------------
extern "C" void kernel_launch(void* const* d_in, const int* in_sizes, int n_in,
                              void* d_out, int out_size) {
    const float* x     = (const float*)d_in[0];
    const int*   ei    = (const int*)d_in[1];
    const float* W1    = (const float*)d_in[2];
    const float* b1    = (const float*)d_in[3];
    const float* W2    = (const float*)d_in[4];
    const float* b2    = (const float*)d_in[5];
    const float* gamma = (const float*)d_in[6];
    const float* beta  = (const float*)d_in[7];
    float* out = (float*)d_out;

    __half *xhi, *mhi, *w1hi, *w2hi, *h2;
    cudaGetSymbolAddress((void**)&xhi, g_xhi);
    cudaGetSymbolAddress((void**)&mhi, g_mhi);
    cudaGetSymbolAddress((void**)&w1hi, g_w1hi);
    cudaGetSymbolAddress((void**)&w2hi, g_w2hi);
    cudaGetSymbolAddress((void**)&h2, g_h2);

    cudaFuncSetAttribute(k_gemm1,
                         cudaFuncAttributeMaxDynamicSharedMemorySize, G1_SMEM);
    cudaFuncSetAttribute(k_gemm2,
                         cudaFuncAttributeMaxDynamicSharedMemorySize, G2_SMEM);

    // CSR build + x->fp16 + aggregate
    k_zero_x2h<<<(NN * DIN / 4 + 255) / 256, 256>>>(x);
    k_hist<<<(NE + 255) / 256, 256>>>(ei);
    k_scan1<<<SCAN_NB, 256>>>();
    k_scan2<<<1, 256>>>();
    k_scan3<<<SCAN_NB, 256>>>();
    k_bucket<<<(NE + 255) / 256, 256>>>(ei);
    k_agg<<<(NN * 32 + 255) / 256, 256>>>();

    // weight prep
    k_prep_w<<<(DIN * DHID + 255) / 256, 256>>>(W1, w1hi, DIN, DHID);
    k_prep_w<<<(DHID * DOUT + 255) / 256, 256>>>(W2, w2hi, DHID, DOUT);

    // GEMM1: [50000x128]@[128x512] -> fp16 (single-shot K)
    {
        dim3 grid(DHID / 128, (NN + 127) / 128);
        k_gemm1<<<grid, 256, G1_SMEM>>>(xhi, w1hi, b1, mhi);
    }
    // GEMM2: [50000x512]@[512x256] -> fp16 (+fused fp32 BN stats)
    {
        dim3 grid(DOUT / 128, (NN + 127) / 128);
        k_gemm2<<<grid, 256, G2_SMEM>>>(mhi, w2hi, b2, h2);
    }
    // normalize (inline BN finalize)
    k_normalize<<<(NN * DOUT / 4 + 255) / 256, 256>>>(out, gamma, beta);
}

// round 15
// speedup vs baseline: 1.5000x; 1.0220x over previous
#include <cuda_runtime.h>
#include <cuda_fp16.h>
#include <cstdint>
#include <cstddef>

#define NN 50000
#define NE 800000
#define DIN 128
#define DHID 512
#define DOUT 256
#define SCAN_NB ((NN + 255) / 256)   // 196

// ---------------------------------------------------------------------------
// Scratch (device globals — no runtime allocation)
// ---------------------------------------------------------------------------
__device__ __half g_xh[(size_t)NN * DIN];        // x fp16 (gather source)
__device__ __half g_xhi[(size_t)NN * DIN];       // (x+agg) fp16
__device__ __half g_h2[(size_t)NN * DOUT];       // after layer2+act (fp16)
__device__ __half g_w1hi[(size_t)DHID * DIN];    // W1^T [N][K] fp16
__device__ __half g_w2hi[(size_t)DOUT * DHID];   // W2^T [N][K] fp16
__device__ float g_sum[DOUT];
__device__ float g_sumsq[DOUT];
// CSR build
__device__ int g_deg[NN];
__device__ int g_off[NN + 1];
__device__ int g_cur[NN];
__device__ int g_srcs[NE];
__device__ int g_blk[SCAN_NB];
__device__ int g_blkoff[SCAN_NB];

// ---------------------------------------------------------------------------
// PTX helpers
// ---------------------------------------------------------------------------
__device__ __forceinline__ uint32_t smem_u32(const void* p) {
    uint32_t a;
    asm("{ .reg .u64 t; cvta.to.shared.u64 t, %1; cvt.u32.u64 %0, t; }"
        : "=r"(a) : "l"(p));
    return a;
}
__device__ __forceinline__ void cp_async16(uint32_t dst, const void* src, bool pred) {
    int sz = pred ? 16 : 0;
    asm volatile("cp.async.cg.shared.global [%0], [%1], 16, %2;"
                 :: "r"(dst), "l"(src), "r"(sz));
}
__device__ __forceinline__ void cp_commit() {
    asm volatile("cp.async.commit_group;" ::: "memory");
}
__device__ __forceinline__ void cp_wait0() {
    asm volatile("cp.async.wait_group 0;" ::: "memory");
}
__device__ __forceinline__ void cp_wait1() {
    asm volatile("cp.async.wait_group 1;" ::: "memory");
}
__device__ __forceinline__ void ldsm_x4(uint32_t* r, uint32_t addr) {
    asm volatile("ldmatrix.sync.aligned.m8n8.x4.shared.b16 {%0,%1,%2,%3}, [%4];"
                 : "=r"(r[0]), "=r"(r[1]), "=r"(r[2]), "=r"(r[3]) : "r"(addr));
}
__device__ __forceinline__ void hmma(float* c, const uint32_t* a, const uint32_t* b) {
    asm volatile(
        "mma.sync.aligned.m16n8k16.row.col.f32.f16.f16.f32 "
        "{%0,%1,%2,%3}, {%4,%5,%6,%7}, {%8,%9}, {%0,%1,%2,%3};"
        : "+f"(c[0]), "+f"(c[1]), "+f"(c[2]), "+f"(c[3])
        : "r"(a[0]), "r"(a[1]), "r"(a[2]), "r"(a[3]), "r"(b[0]), "r"(b[1]));
}

// ---------------------------------------------------------------------------
// 0) zero + x->fp16 + both weight transposes (one launch)
// ---------------------------------------------------------------------------
__global__ void k_zero_prep(const float* __restrict__ x,
                            const float* __restrict__ W1,
                            const float* __restrict__ W2) {
    int i = blockIdx.x * blockDim.x + threadIdx.x;
    if (i < NN) g_deg[i] = 0;
    if (i < DOUT) { g_sum[i] = 0.f; g_sumsq[i] = 0.f; }
    if (i < DIN * DHID) {           // W1^T
        int n = i / DIN, k = i % DIN;
        g_w1hi[i] = __float2half_rn(W1[(size_t)k * DHID + n]);
    }
    if (i < DHID * DOUT) {          // W2^T
        int n = i / DHID, k = i % DHID;
        g_w2hi[i] = __float2half_rn(W2[(size_t)k * DOUT + n]);
    }
    const int n4 = NN * DIN / 4;
    if (i < n4) {
        float4 v = reinterpret_cast<const float4*>(x)[i];
        __half2* o = reinterpret_cast<__half2*>(g_xh) + i * 2;
        o[0] = __halves2half2(__float2half_rn(v.x), __float2half_rn(v.y));
        o[1] = __halves2half2(__float2half_rn(v.z), __float2half_rn(v.w));
    }
}

// ---------------------------------------------------------------------------
// 1) histogram of dst degrees
// ---------------------------------------------------------------------------
__global__ void k_hist(const int* __restrict__ ei) {
    int e = blockIdx.x * blockDim.x + threadIdx.x;
    if (e < NE) atomicAdd(&g_deg[ei[NE + e]], 1);
}

// ---------------------------------------------------------------------------
// 2) parallel exclusive scan, 3 phases
// ---------------------------------------------------------------------------
__global__ void __launch_bounds__(256) k_scan1() {
    __shared__ int s[256];
    int i = blockIdx.x * 256 + threadIdx.x;
    int v = (i < NN) ? g_deg[i] : 0;
    s[threadIdx.x] = v;
    __syncthreads();
    #pragma unroll
    for (int d = 128; d > 0; d >>= 1) {
        if (threadIdx.x < d) s[threadIdx.x] += s[threadIdx.x + d];
        __syncthreads();
    }
    if (threadIdx.x == 0) g_blk[blockIdx.x] = s[0];
}

__global__ void __launch_bounds__(256) k_scan2() {
    __shared__ int s[256];
    int t = threadIdx.x;
    int v = (t < SCAN_NB) ? g_blk[t] : 0;
    s[t] = v;
    __syncthreads();
    #pragma unroll
    for (int d = 1; d < 256; d <<= 1) {
        int u = (t >= d) ? s[t - d] : 0;
        __syncthreads();
        s[t] += u;
        __syncthreads();
    }
    if (t < SCAN_NB) g_blkoff[t] = s[t] - v;
    if (t == 0) g_off[NN] = NE;
}

__global__ void __launch_bounds__(256) k_scan3() {
    __shared__ int s[256];
    int t = threadIdx.x;
    int i = blockIdx.x * 256 + t;
    int v = (i < NN) ? g_deg[i] : 0;
    s[t] = v;
    __syncthreads();
    #pragma unroll
    for (int d = 1; d < 256; d <<= 1) {
        int u = (t >= d) ? s[t - d] : 0;
        __syncthreads();
        s[t] += u;
        __syncthreads();
    }
    if (i < NN) {
        int off = g_blkoff[blockIdx.x] + s[t] - v;
        g_off[i] = off;
        g_cur[i] = off;
    }
}

// ---------------------------------------------------------------------------
// 3) bucket edges by dst
// ---------------------------------------------------------------------------
__global__ void k_bucket(const int* __restrict__ ei) {
    int e = blockIdx.x * blockDim.x + threadIdx.x;
    if (e >= NE) return;
    int dst = ei[NE + e];
    int pos = atomicAdd(&g_cur[dst], 1);
    g_srcs[pos] = ei[e];
}

// ---------------------------------------------------------------------------
// 4) aggregate: one warp per node; fp16 gather, fp32 accumulate, fp16 out
// ---------------------------------------------------------------------------
__global__ void __launch_bounds__(256) k_agg() {
    int w = (blockIdx.x * blockDim.x + threadIdx.x) >> 5;
    if (w >= NN) return;
    int lane = threadIdx.x & 31;

    float acc0, acc1, acc2, acc3;
    {
        uint2 v = *reinterpret_cast<const uint2*>(g_xh + (size_t)w * DIN + lane * 4);
        float2 f0 = __half22float2(*reinterpret_cast<__half2*>(&v.x));
        float2 f1 = __half22float2(*reinterpret_cast<__half2*>(&v.y));
        acc0 = f0.x; acc1 = f0.y; acc2 = f1.x; acc3 = f1.y;
    }
    int beg = g_off[w], end = g_off[w + 1];
    for (int base = beg; base < end; base += 32) {
        int n = end - base;
        if (n > 32) n = 32;
        int s = (lane < n) ? g_srcs[base + lane] : 0;
        #pragma unroll 4
        for (int j = 0; j < n; j++) {
            int src = __shfl_sync(0xffffffffu, s, j);
            uint2 v = *reinterpret_cast<const uint2*>(g_xh + (size_t)src * DIN + lane * 4);
            float2 f0 = __half22float2(*reinterpret_cast<__half2*>(&v.x));
            float2 f1 = __half22float2(*reinterpret_cast<__half2*>(&v.y));
            acc0 += f0.x; acc1 += f0.y; acc2 += f1.x; acc3 += f1.y;
        }
    }
    __half2* o = reinterpret_cast<__half2*>(g_xhi + (size_t)w * DIN + lane * 4);
    o[0] = __halves2half2(__float2half_rn(acc0), __float2half_rn(acc1));
    o[1] = __halves2half2(__float2half_rn(acc2), __float2half_rn(acc3));
}

// ---------------------------------------------------------------------------
// 5) FUSED MLP: per CTA m-block of 64 rows.
//    Phase 1: hmid(64x512) = lrelu(x @ W1^T + b1)  -> smem (fp16)
//    Phase 2: h2(64x256)   = lrelu(hmid @ W2^T + b2) -> global fp16 + BN stats
//    2 CTAs/SM; A of phase 2 never touches global memory.
// ---------------------------------------------------------------------------
#define FM 64
#define HROWB 1040                   // 512*2 + 16 pad (16B aligned, ldsm-safe)
#define HM_SZ (FM * HROWB)           // 66560
#define SC_OFF HM_SZ                 // scratch region base
#define XB_SZ (FM * 272)             // 17408 (x tile, 272B rows)
#define W1_STG 17408                 // 64 n-rows x 272B
#define B2_STG (256 * 80)            // 20480 (W2 chunk: 256 rows x 80B)
#define SC_SZ (2 * B2_STG)           // 40960 >= max(XB, 2*W1_STG, 2*B2_STG)
#define FU_SMEM (HM_SZ + SC_SZ)      // 107520 -> 2 CTAs/SM

__global__ void __launch_bounds__(256, 2)
k_fused(const __half* __restrict__ Ah, const __half* __restrict__ W1t,
        const float* __restrict__ b1, const __half* __restrict__ W2t,
        const float* __restrict__ b2, __half* __restrict__ Ch) {
    extern __shared__ char smem[];
    const uint32_t sb = smem_u32(smem);
    const int tid = threadIdx.x;
    const int wid = tid >> 5;
    const int lane = tid & 31;
    const int m0 = blockIdx.x * FM;
    const int M = NN;
    const uint32_t lrow = (uint32_t)(lane & 15);
    const uint32_t lchk = (uint32_t)(lane >> 4);
    const int warp_m = wid & 1;      // 2 m-groups of 32 rows
    const int warp_n = wid >> 1;     // 4 n-groups

    // ---- load x tile (64 x 128 fp16) into scratch[0..XB_SZ)
    #pragma unroll
    for (int it = 0; it < 4; it++) {
        int idx = tid + it * 256;        // 0..1023
        int row = idx >> 4;              // 0..63
        int c = idx & 15;
        int gmr = m0 + row;
        cp_async16(sb + SC_OFF + row * 272 + c * 16,
                   Ah + (size_t)gmr * DIN + c * 8, gmr < M);
    }
    cp_commit();
    cp_wait0();
    __syncthreads();

    // ---- preload A fragments for the whole K=128 (a1 dead after phase 1)
    uint32_t a1[2][8][4];
    #pragma unroll
    for (int mt = 0; mt < 2; mt++)
        #pragma unroll
        for (int ks = 0; ks < 8; ks++) {
            uint32_t r = (uint32_t)(warp_m * 32 + mt * 16) + lrow;
            ldsm_x4(a1[mt][ks], sb + SC_OFF + r * 272 + lchk * 16 + ks * 32);
        }
    __syncthreads();                     // x tile region free

    // ---- phase 1: 8 chunks of 64 output cols, W1^T ring (2 stages)
    auto load_w1 = [&](int ch) {
        const uint32_t stg = sb + SC_OFF + (ch & 1) * W1_STG;
        #pragma unroll
        for (int it = 0; it < 4; it++) {
            int idx = tid + it * 256;
            int row = idx >> 4;          // 0..63 (n-row within chunk)
            int c = idx & 15;
            cp_async16(stg + row * 272 + c * 16,
                       W1t + (size_t)(ch * 64 + row) * DIN + c * 8, true);
        }
        cp_commit();
    };

    load_w1(0);
    for (int ch = 0; ch < 8; ch++) {
        if (ch + 1 < 8) { load_w1(ch + 1); cp_wait1(); }
        else cp_wait0();
        __syncthreads();

        const uint32_t stg = sb + SC_OFF + (ch & 1) * W1_STG;
        float acc1[2][2][4];
        #pragma unroll
        for (int a = 0; a < 2; a++)
            #pragma unroll
            for (int b = 0; b < 2; b++)
                #pragma unroll
                for (int c = 0; c < 4; c++) acc1[a][b][c] = 0.f;

        #pragma unroll
        for (int ks = 0; ks < 8; ks++) {
            uint32_t bh[4];
            uint32_t r = (uint32_t)(warp_n * 16) + lrow;
            ldsm_x4(bh, stg + r * 272 + lchk * 16 + ks * 32);
            uint32_t b0h[2] = {bh[0], bh[2]}, b1h[2] = {bh[1], bh[3]};
            #pragma unroll
            for (int mt = 0; mt < 2; mt++) {
                hmma(acc1[mt][0], a1[mt][ks], b0h);
                hmma(acc1[mt][1], a1[mt][ks], b1h);
            }
        }
        // epilogue -> smem hmid (bias + lrelu + fp16)
        #pragma unroll
        for (int mt = 0; mt < 2; mt++) {
            int row = warp_m * 32 + mt * 16 + (lane >> 2);
            #pragma unroll
            for (int cf = 0; cf < 2; cf++) {
                int col = ch * 64 + warp_n * 16 + cf * 8 + 2 * (lane & 3);
                float bx = b1[col], by = b1[col + 1];
                #pragma unroll
                for (int h = 0; h < 2; h++) {
                    int r = row + h * 8;
                    float v0 = acc1[mt][cf][2 * h + 0] + bx;
                    float v1 = acc1[mt][cf][2 * h + 1] + by;
                    v0 = v0 > 0.f ? v0 : 0.01f * v0;
                    v1 = v1 > 0.f ? v1 : 0.01f * v1;
                    *reinterpret_cast<__half2*>(smem + r * HROWB + col * 2) =
                        __halves2half2(__float2half_rn(v0), __float2half_rn(v1));
                }
            }
        }
        __syncthreads();
    }

    // ---- phase 2: (64x512) @ W2^T(256x512) -> 64x256, K chunks of 32
    float acc[2][8][4];
    #pragma unroll
    for (int a = 0; a < 2; a++)
        #pragma unroll
        for (int b = 0; b < 8; b++)
            #pragma unroll
            for (int c = 0; c < 4; c++) acc[a][b][c] = 0.f;

    auto load_b2 = [&](int ch) {
        const uint32_t stg = sb + SC_OFF + (ch & 1) * B2_STG;
        #pragma unroll
        for (int it = 0; it < 4; it++) {
            int idx = tid + it * 256;    // 0..1023
            int row = idx >> 2;          // 0..255
            int c = idx & 3;
            cp_async16(stg + row * 80 + c * 16,
                       W2t + (size_t)row * DHID + ch * 32 + c * 8, true);
        }
        cp_commit();
    };

    load_b2(0);
    for (int ch = 0; ch < 16; ch++) {
        if (ch + 1 < 16) { load_b2(ch + 1); cp_wait1(); }
        else cp_wait0();
        __syncthreads();

        const uint32_t stg = sb + SC_OFF + (ch & 1) * B2_STG;
        #pragma unroll
        for (int ks = 0; ks < 2; ks++) {
            uint32_t a2[2][4];
            #pragma unroll
            for (int mt = 0; mt < 2; mt++) {
                uint32_t r = (uint32_t)(warp_m * 32 + mt * 16) + lrow;
                ldsm_x4(a2[mt], sb + r * HROWB + ch * 64 + ks * 32 + lchk * 16);
            }
            #pragma unroll
            for (int np = 0; np < 4; np++) {
                uint32_t bh[4];
                uint32_t r = (uint32_t)(warp_n * 64 + np * 16) + lrow;
                ldsm_x4(bh, stg + r * 80 + lchk * 16 + ks * 32);
                uint32_t b0h[2] = {bh[0], bh[2]}, b1h[2] = {bh[1], bh[3]};
                #pragma unroll
                for (int mt = 0; mt < 2; mt++) {
                    hmma(acc[mt][2 * np],     a2[mt], b0h);
                    hmma(acc[mt][2 * np + 1], a2[mt], b1h);
                }
            }
        }
        __syncthreads();
    }

    // ---- epilogue: bias + lrelu + fp16 store + fused BN stats
    float scol[8][2];
    float qcol[8][2];
    #pragma unroll
    for (int nt = 0; nt < 8; nt++) {
        scol[nt][0] = scol[nt][1] = 0.f;
        qcol[nt][0] = qcol[nt][1] = 0.f;
    }

    #pragma unroll
    for (int mt = 0; mt < 2; mt++) {
        int row = m0 + warp_m * 32 + mt * 16 + (lane >> 2);
        #pragma unroll
        for (int nt = 0; nt < 8; nt++) {
            int col = warp_n * 64 + nt * 8 + 2 * (lane & 3);
            float bx = b2[col], by = b2[col + 1];
            #pragma unroll
            for (int h = 0; h < 2; h++) {
                int r = row + h * 8;
                if (r >= M) continue;
                float v0 = acc[mt][nt][2 * h + 0] + bx;
                float v1 = acc[mt][nt][2 * h + 1] + by;
                v0 = v0 > 0.f ? v0 : 0.01f * v0;
                v1 = v1 > 0.f ? v1 : 0.01f * v1;
                *reinterpret_cast<__half2*>(Ch + (size_t)r * DOUT + col) =
                    __halves2half2(__float2half_rn(v0), __float2half_rn(v1));
                scol[nt][0] += v0; qcol[nt][0] += v0 * v0;
                scol[nt][1] += v1; qcol[nt][1] += v1 * v1;
            }
        }
    }

    {
        float* sarr = reinterpret_cast<float*>(smem + SC_OFF);
        float* qarr = sarr + DOUT;
        __syncthreads();
        if (tid < DOUT) { sarr[tid] = 0.f; qarr[tid] = 0.f; }
        __syncthreads();
        #pragma unroll
        for (int nt = 0; nt < 8; nt++) {
            float s0 = scol[nt][0], s1 = scol[nt][1];
            float q0 = qcol[nt][0], q1 = qcol[nt][1];
            #pragma unroll
            for (int o = 4; o < 32; o <<= 1) {
                s0 += __shfl_xor_sync(0xffffffffu, s0, o);
                s1 += __shfl_xor_sync(0xffffffffu, s1, o);
                q0 += __shfl_xor_sync(0xffffffffu, q0, o);
                q1 += __shfl_xor_sync(0xffffffffu, q1, o);
            }
            if (lane < 4) {
                int c = warp_n * 64 + nt * 8 + 2 * lane;
                atomicAdd(&sarr[c], s0);
                atomicAdd(&sarr[c + 1], s1);
                atomicAdd(&qarr[c], q0);
                atomicAdd(&qarr[c + 1], q1);
            }
        }
        __syncthreads();
        if (tid < DOUT) {
            atomicAdd(&g_sum[tid], sarr[tid]);
            atomicAdd(&g_sumsq[tid], qarr[tid]);
        }
    }
}

// ---------------------------------------------------------------------------
// 6) normalize with inline BN finalize (fp16 h2 in, fp32 out)
// ---------------------------------------------------------------------------
__global__ void __launch_bounds__(256) k_normalize(float* __restrict__ out,
                                                   const float* __restrict__ gamma,
                                                   const float* __restrict__ beta) {
    __shared__ float4 s_sc[DOUT / 4];
    __shared__ float4 s_sh[DOUT / 4];
    const int tid = threadIdx.x;
    if (tid < DOUT / 4) {
        const float invn = 1.0f / (float)NN;
        float4 sc, sh;
        #pragma unroll
        for (int k = 0; k < 4; k++) {
            int c = tid * 4 + k;
            float mean = g_sum[c] * invn;
            float var = g_sumsq[c] * invn - mean * mean;
            float rstd = rsqrtf(var + 1e-5f);
            float s = gamma[c] * rstd;
            (&sc.x)[k] = s;
            (&sh.x)[k] = beta[c] - mean * s;
        }
        s_sc[tid] = sc;
        s_sh[tid] = sh;
    }
    __syncthreads();

    int i = blockIdx.x * blockDim.x + tid;
    const int n4 = NN * DOUT / 4;
    if (i >= n4) return;
    int c4 = i & (DOUT / 4 - 1);
    uint2 hv = reinterpret_cast<const uint2*>(g_h2)[i];
    float2 f0 = __half22float2(*reinterpret_cast<__half2*>(&hv.x));
    float2 f1 = __half22float2(*reinterpret_cast<__half2*>(&hv.y));
    float4 sc = s_sc[c4];
    float4 sh = s_sh[c4];
    float4 v;
    v.x = f0.x * sc.x + sh.x;
    v.y = f0.y * sc.y + sh.y;
    v.z = f1.x * sc.z + sh.z;
    v.w = f1.y * sc.w + sh.w;
    reinterpret_cast<float4*>(out)[i] = v;
}

// ---------------------------------------------------------------------------
extern "C" void kernel_launch(void* const* d_in, const int* in_sizes, int n_in,
                              void* d_out, int out_size) {
    const float* x     = (const float*)d_in[0];
    const int*   ei    = (const int*)d_in[1];
    const float* W1    = (const float*)d_in[2];
    const float* b1    = (const float*)d_in[3];
    const float* W2    = (const float*)d_in[4];
    const float* b2    = (const float*)d_in[5];
    const float* gamma = (const float*)d_in[6];
    const float* beta  = (const float*)d_in[7];
    float* out = (float*)d_out;

    __half *xhi, *w1hi, *w2hi, *h2;
    cudaGetSymbolAddress((void**)&xhi, g_xhi);
    cudaGetSymbolAddress((void**)&w1hi, g_w1hi);
    cudaGetSymbolAddress((void**)&w2hi, g_w2hi);
    cudaGetSymbolAddress((void**)&h2, g_h2);

    cudaFuncSetAttribute(k_fused,
                         cudaFuncAttributeMaxDynamicSharedMemorySize, FU_SMEM);

    // CSR build + x->fp16 + weight prep + aggregate
    k_zero_prep<<<(NN * DIN / 4 + 255) / 256, 256>>>(x, W1, W2);
    k_hist<<<(NE + 255) / 256, 256>>>(ei);
    k_scan1<<<SCAN_NB, 256>>>();
    k_scan2<<<1, 256>>>();
    k_scan3<<<SCAN_NB, 256>>>();
    k_bucket<<<(NE + 255) / 256, 256>>>(ei);
    k_agg<<<(NN * 32 + 255) / 256, 256>>>();

    // fused MLP (GEMM1 + GEMM2 + BN stats)
    k_fused<<<(NN + FM - 1) / FM, 256, FU_SMEM>>>(xhi, w1hi, b1, w2hi, b2, h2);

    // normalize (inline BN finalize)
    k_normalize<<<(NN * DOUT / 4 + 255) / 256, 256>>>(out, gamma, beta);
}